// round 15
// baseline (speedup 1.0000x reference)
#include <cuda_runtime.h>
#include <math.h>

#define N_MAX 100000
#define E_MAX 1600000
#define G_NUM 1024
#define NCHUNK_MAX 128   // ceil(100000/1024)=98

// ---------------- device scratch (no allocation allowed) -------------------
__device__ __align__(16) float g_B0[(long long)N_MAX * 64]; // ping
__device__ __align__(16) float g_B1[(long long)N_MAX * 64]; // pong
__device__ float g_dinv[N_MAX];
__device__ int   g_deg [N_MAX];        // zero at entry (static init + re-zero)
__device__ int   g_tmp [N_MAX];        // chunk-inclusive scan values
__device__ int   g_off [N_MAX + 1];    // CSR offsets (by dst)
__device__ int   g_bsum[NCHUNK_MAX];   // per-chunk sums
__device__ int   g_pos [E_MAX];        // per-edge rank within dst bucket
__device__ int   g_csrc[E_MAX];        // CSR src ids
__device__ float g_pool[G_NUM * 64];
__device__ int   g_barCount = 0;       // grid barrier state
__device__ int   g_barSense = 0;       // must be 0 at entry (even #barriers)

// ------------------------- grid-wide barrier --------------------------------
__device__ __forceinline__ void gbar(int nblocks, int* sense) {
    __syncthreads();
    if (threadIdx.x == 0) {
        int next = *sense ^ 1;
        __threadfence();
        if (atomicAdd(&g_barCount, 1) == nblocks - 1) {
            g_barCount = 0;
            __threadfence();
            *(volatile int*)&g_barSense = next;
        } else {
            while (*(volatile int*)&g_barSense != next) { __nanosleep(64); }
            __threadfence();
        }
        *sense = next;
    }
    __syncthreads();
}

// ------------------------- phase helpers ------------------------------------
// transform: acc = in @ W ; EPI 0: raw, 1: relu(+b)*dinv, 2: relu(+b)
template <int F_IN, int F_OUT, int EPI>
__device__ void transform_phase(const float* __restrict__ in, float* __restrict__ outb,
                                const float* __restrict__ W,
                                const float* __restrict__ bout, int n, float* sW)
{
    for (int i = threadIdx.x; i < F_IN * F_OUT; i += 256) sW[i] = W[i];
    __syncthreads();
    for (int node = blockIdx.x * 256 + threadIdx.x; node < n; node += gridDim.x * 256) {
        const float4* row4 = reinterpret_cast<const float4*>(in) +
                             (long long)node * (F_IN / 4);
        float acc[F_OUT];
#pragma unroll
        for (int j = 0; j < F_OUT; j++) acc[j] = 0.f;
        for (int k4 = 0; k4 < F_IN / 4; k4++) {
            float4 v4 = row4[k4];
            float vv[4] = {v4.x, v4.y, v4.z, v4.w};
#pragma unroll
            for (int u = 0; u < 4; u++) {
                int k = k4 * 4 + u;
#pragma unroll
                for (int j = 0; j < F_OUT; j++)
                    acc[j] = fmaf(vv[u], sW[k * F_OUT + j], acc[j]);
            }
        }
        float di = (EPI == 1) ? g_dinv[node] : 1.f;
        float4* out4 = reinterpret_cast<float4*>(outb) + (long long)node * (F_OUT / 4);
#pragma unroll
        for (int j4 = 0; j4 < F_OUT / 4; j4++) {
            float o[4];
#pragma unroll
            for (int u = 0; u < 4; u++) {
                float a = acc[j4 * 4 + u];
                if (EPI == 0)      o[u] = a;
                else if (EPI == 1) o[u] = fmaxf(a + bout[j4 * 4 + u], 0.f) * di;
                else               o[u] = fmaxf(a + bout[j4 * 4 + u], 0.f);
            }
            out4[j4] = make_float4(o[0], o[1], o[2], o[3]);
        }
    }
}

// warp-per-node gather, x2-unrolled edge loop, shfl cross-slot reduction
template <int L, bool FUSED>
__device__ void gather_phase(const float* __restrict__ inb, float* __restrict__ outb,
                             const float* __restrict__ bias, int n)
{
    constexpr int SLOTS = 32 / L;
    int warp = threadIdx.x >> 5;
    int lane = threadIdx.x & 31;
    int slot = lane / L;
    int f4   = lane % L;
    const float4* In4 = reinterpret_cast<const float4*>(inb);
    float4* Out4 = reinterpret_cast<float4*>(outb);

    for (int node = blockIdx.x * 8 + warp; node < n; node += gridDim.x * 8) {
        int e0 = g_off[node];
        int e1 = g_off[node + 1];
        float4 a = make_float4(0.f, 0.f, 0.f, 0.f);
        float4 b = make_float4(0.f, 0.f, 0.f, 0.f);
        if (slot == 0) a = In4[(long long)node * L + f4];   // self-loop

        int e = e0 + slot;
        for (; e + SLOTS < e1; e += 2 * SLOTS) {
            int s0 = g_csrc[e];
            int s1 = g_csrc[e + SLOTS];
            float4 v0 = In4[(long long)s0 * L + f4];
            float4 v1 = In4[(long long)s1 * L + f4];
            a.x += v0.x; a.y += v0.y; a.z += v0.z; a.w += v0.w;
            b.x += v1.x; b.y += v1.y; b.z += v1.z; b.w += v1.w;
        }
        if (e < e1) {
            int s0 = g_csrc[e];
            float4 v0 = In4[(long long)s0 * L + f4];
            a.x += v0.x; a.y += v0.y; a.z += v0.z; a.w += v0.w;
        }
        a.x += b.x; a.y += b.y; a.z += b.z; a.w += b.w;

#pragma unroll
        for (int off = 16; off >= L; off >>= 1) {
            a.x += __shfl_xor_sync(0xffffffffu, a.x, off);
            a.y += __shfl_xor_sync(0xffffffffu, a.y, off);
            a.z += __shfl_xor_sync(0xffffffffu, a.z, off);
            a.w += __shfl_xor_sync(0xffffffffu, a.w, off);
        }
        if (slot == 0) {
            float di = g_dinv[node];
            float4 o;
            o.x = a.x * di; o.y = a.y * di; o.z = a.z * di; o.w = a.w * di;
            if (FUSED) {
                const float4 b4 = reinterpret_cast<const float4*>(bias)[f4];
                o.x = fmaxf(o.x + b4.x, 0.f) * di;
                o.y = fmaxf(o.y + b4.y, 0.f) * di;
                o.z = fmaxf(o.z + b4.z, 0.f) * di;
                o.w = fmaxf(o.w + b4.w, 0.f) * di;
            }
            Out4[(long long)node * L + f4] = o;
        }
    }
}

// ------------------------------ mega kernel ---------------------------------
__global__ void __launch_bounds__(256, 1)
k_mega(const float* __restrict__ x, const int* __restrict__ ei,
       const int* __restrict__ batch,
       const float* __restrict__ W1, const float* __restrict__ b1,
       const float* __restrict__ W2, const float* __restrict__ b2,
       const float* __restrict__ W3, const float* __restrict__ b3,
       const float* __restrict__ L1w, const float* __restrict__ L1b,
       const float* __restrict__ L2w, const float* __restrict__ L2b,
       float* __restrict__ out, int N, int E, int nChunk, int nBlocks)
{
    __shared__ float sh[2048];                     // union: sW / scan / mlp
    int* shi = reinterpret_cast<int*>(sh);
    int t = threadIdx.x;
    int gstride = gridDim.x * 256;
    int gid = blockIdx.x * 256 + t;
    int sense = 0;

    // ---- Phase A: transform1 raw (x@W1 -> B0) + edge rank/degree ----------
    transform_phase<128, 16, 0>(x, g_B0, W1, nullptr, N, sh);
    for (int e = gid; e < E; e += gstride)
        g_pos[e] = atomicAdd(&g_deg[ei[E + e]], 1);
    gbar(nBlocks, &sense);                                            // 1

    // ---- Phase B: chunked inclusive scan of degrees (1024/chunk) ----------
    for (int c = blockIdx.x; c < nChunk; c += gridDim.x) {
        int base = c * 1024 + t * 4;
        int a0 = (base + 0 < N) ? g_deg[base + 0] : 0;
        int a1 = (base + 1 < N) ? g_deg[base + 1] : 0;
        int a2 = (base + 2 < N) ? g_deg[base + 2] : 0;
        int a3 = (base + 3 < N) ? g_deg[base + 3] : 0;
        int p1 = a0 + a1, p2 = p1 + a2, p3 = p2 + a3;
        shi[t] = p3;
        __syncthreads();
#pragma unroll
        for (int d = 1; d < 256; d <<= 1) {
            int v = (t >= d) ? shi[t - d] : 0;
            __syncthreads();
            shi[t] += v;
            __syncthreads();
        }
        int excl = (t > 0) ? shi[t - 1] : 0;
        if (base + 0 < N) g_tmp[base + 0] = excl + a0;
        if (base + 1 < N) g_tmp[base + 1] = excl + p1;
        if (base + 2 < N) g_tmp[base + 2] = excl + p2;
        if (base + 3 < N) g_tmp[base + 3] = excl + p3;
        if (t == 255) g_bsum[c] = shi[255];
        __syncthreads();
    }
    gbar(nBlocks, &sense);                                            // 2

    // ---- Phase C: offsets + dinv + pool zero (each block scans bsum) ------
    shi[t] = (t < NCHUNK_MAX && t < nChunk) ? g_bsum[t] : 0;
    __syncthreads();
#pragma unroll
    for (int d = 1; d < NCHUNK_MAX; d <<= 1) {
        int v = (t < NCHUNK_MAX && t >= d) ? shi[t - d] : 0;
        __syncthreads();
        if (t < NCHUNK_MAX) shi[t] += v;
        __syncthreads();
    }
    for (int i = gid; i < N; i += gstride) {
        int deg = g_deg[i];
        int blk = i >> 10;
        int base = (blk == 0) ? 0 : shi[blk - 1];
        g_off[i] = g_tmp[i] - deg + base;
        g_dinv[i] = rsqrtf((float)(deg + 1));
    }
    for (int i = gid; i < G_NUM * 64; i += gstride) g_pool[i] = 0.f;
    if (gid == 0) g_off[N] = E;
    gbar(nBlocks, &sense);                                            // 3

    // ---- Phase D: place edges + prescale B0 by dinv + deg re-zero ---------
    {
        float4* B04 = reinterpret_cast<float4*>(g_B0);
        for (int idx = gid; idx < N * 4; idx += gstride) {
            int node = idx >> 2;
            float d = g_dinv[node];
            float4 v = B04[idx];
            v.x *= d; v.y *= d; v.z *= d; v.w *= d;
            B04[idx] = v;
        }
    }
    for (int e = gid; e < E; e += gstride)
        g_csrc[g_off[ei[E + e]] + g_pos[e]] = ei[e];
    for (int i = gid; i < N; i += gstride) g_deg[i] = 0;
    gbar(nBlocks, &sense);                                            // 4

    // ---- Phase E: gather1 fused (B0 -> B1, relu(+b1)*dinv), F=16 ----------
    gather_phase<4, true>(g_B0, g_B1, b1, N);
    gbar(nBlocks, &sense);                                            // 5

    // ---- Phase F: gather2 (B1 -> B0, m2), F=16 -----------------------------
    gather_phase<4, false>(g_B1, g_B0, nullptr, N);
    gbar(nBlocks, &sense);                                            // 6

    // ---- Phase G: transform2 (B0 -> B1, relu(m2@W2+b2)*dinv) ---------------
    transform_phase<16, 32, 1>(g_B0, g_B1, W2, b2, N, sh);
    gbar(nBlocks, &sense);                                            // 7

    // ---- Phase H: gather3 (B1 -> B0, m3), F=32 -----------------------------
    gather_phase<8, false>(g_B1, g_B0, nullptr, N);
    gbar(nBlocks, &sense);                                            // 8

    // ---- Phase I: transform3 (B0 -> B1, relu(m3@W3+b3)) --------------------
    transform_phase<32, 64, 2>(g_B0, g_B1, W3, b3, N, sh);
    gbar(nBlocks, &sense);                                            // 9

    // ---- Phase J: pool (segment max over sorted batch) ---------------------
    {
        int f = t & 63, sub = t >> 6;
        int nchunks = (N + 15) / 16;
        for (int chunk = blockIdx.x * 4 + sub; chunk < nchunks; chunk += gridDim.x * 4) {
            int n0 = chunk * 16;
            int n1 = min(n0 + 16, N);
            int curg = batch[n0];
            float m = g_B1[(long long)n0 * 64 + f];
            for (int i = n0 + 1; i < n1; i++) {
                int g = batch[i];
                float v = g_B1[(long long)i * 64 + f];
                if (g != curg) {
                    atomicMax((unsigned int*)&g_pool[curg * 64 + f], __float_as_uint(m));
                    curg = g; m = v;
                } else {
                    m = fmaxf(m, v);
                }
            }
            atomicMax((unsigned int*)&g_pool[curg * 64 + f], __float_as_uint(m));
        }
    }
    gbar(nBlocks, &sense);                                            // 10 (even)

    // ---- Phase K: MLP head (block-stride over graphs) ----------------------
    for (int g = blockIdx.x; g < G_NUM; g += gridDim.x) {
        if (t < 64) sh[t] = g_pool[g * 64 + t];
        __syncthreads();
        float acc = L1b[t];
#pragma unroll
        for (int k = 0; k < 64; k++) acc = fmaf(sh[k], L1w[k * 256 + t], acc);
        sh[64 + t] = fmaxf(acc, 0.f);
        __syncthreads();
        float acc2 = L2b[t];
#pragma unroll 8
        for (int k = 0; k < 256; k++) acc2 = fmaf(sh[64 + k], L2w[k * 256 + t], acc2);
        out[(long long)g * 256 + t] = 1.f / (1.f + expf(-acc2));
        __syncthreads();
    }
}

// ------------------------------ launch -------------------------------------
extern "C" void kernel_launch(void* const* d_in, const int* in_sizes, int n_in,
                              void* d_out, int out_size)
{
    const float* x     = (const float*)d_in[0];
    const int*   ei    = (const int*)d_in[1];    // int32 (JAX x64 disabled)
    const int*   batch = (const int*)d_in[2];
    const float* W1 = (const float*)d_in[3];
    const float* b1 = (const float*)d_in[4];
    const float* W2 = (const float*)d_in[5];
    const float* b2 = (const float*)d_in[6];
    const float* W3 = (const float*)d_in[7];
    const float* b3 = (const float*)d_in[8];
    const float* L1w = (const float*)d_in[9];
    const float* L1b = (const float*)d_in[10];
    const float* L2w = (const float*)d_in[11];
    const float* L2b = (const float*)d_in[12];
    float* out = (float*)d_out;

    int N = in_sizes[0] / 128;
    int E = in_sizes[1] / 2;
    int nChunk = (N + 1023) / 1024;

    int dev = 0;
    cudaGetDevice(&dev);
    int sms = 0;
    cudaDeviceGetAttribute(&sms, cudaDevAttrMultiProcessorCount, dev);
    int occ = 0;
    cudaOccupancyMaxActiveBlocksPerMultiprocessor(&occ, k_mega, 256, 0);
    if (occ < 1) occ = 1;
    if (occ > 4) occ = 4;                 // cap: barrier cost vs parallelism
    int blocks = sms * occ;

    k_mega<<<blocks, 256>>>(x, ei, batch, W1, b1, W2, b2, W3, b3,
                            L1w, L1b, L2w, L2b, out, N, E, nChunk, blocks);
}

// round 16
// speedup vs baseline: 2.4601x; 2.4601x over previous
#include <cuda_runtime.h>
#include <math.h>

#define N_MAX 100000
#define E_MAX 1600000
#define G_NUM 1024
#define SCAN_B 1024
#define NBLK_MAX 128   // ceil(100000/1024)=98

// ---------------- device scratch (no allocation allowed) -------------------
__device__ __align__(16) float g_B0[(long long)N_MAX * 64]; // ping
__device__ __align__(16) float g_B1[(long long)N_MAX * 64]; // pong
__device__ float g_dinv[N_MAX];
__device__ int   g_deg [N_MAX];        // MUST be zero at entry of every call
                                       // (static zero-init; re-zeroed in k_place)
__device__ int   g_tmp [N_MAX];        // block-scan partials
__device__ int   g_off [N_MAX + 1];    // CSR offsets (by dst)
__device__ int   g_bsum[NBLK_MAX];     // block sums for scan
__device__ int   g_pos [E_MAX];        // per-edge rank within dst bucket
__device__ int   g_csrc[E_MAX];        // CSR src ids
__device__ float g_pool[G_NUM * 64];

__device__ __forceinline__ float* buf(int s) { return s == 0 ? g_B0 : g_B1; }

// ---------------------------------------------------------------------------
// kA (block-split): blocks [0,tB) -> transform1 RAW (q0_raw = x @ W1 -> B0);
//                   blocks [tB,..) -> edge rank pass (deg count + rank).
// The two sides are independent; splitting lets them overlap on-chip instead
// of serializing across kernel boundaries.
// ---------------------------------------------------------------------------
__global__ void kA(const float* __restrict__ x, const float* __restrict__ W1,
                   const int* __restrict__ ei, int N, int E, int tB)
{
    if ((int)blockIdx.x < tB) {
        __shared__ float sW[128 * 16];
        for (int i = threadIdx.x; i < 128 * 16; i += blockDim.x) sW[i] = W1[i];
        __syncthreads();
        int node = blockIdx.x * 256 + threadIdx.x;
        if (node >= N) return;

        const float4* row4 = reinterpret_cast<const float4*>(x) + (long long)node * 32;
        float acc[16];
#pragma unroll
        for (int j = 0; j < 16; j++) acc[j] = 0.f;
        for (int k4 = 0; k4 < 32; k4++) {
            float4 v4 = row4[k4];
            float vv[4] = {v4.x, v4.y, v4.z, v4.w};
#pragma unroll
            for (int u = 0; u < 4; u++) {
                int k = k4 * 4 + u;
#pragma unroll
                for (int j = 0; j < 16; j++)
                    acc[j] = fmaf(vv[u], sW[k * 16 + j], acc[j]);
            }
        }
        float4* out4 = reinterpret_cast<float4*>(g_B0) + (long long)node * 4;
#pragma unroll
        for (int j4 = 0; j4 < 4; j4++)
            out4[j4] = make_float4(acc[j4*4+0], acc[j4*4+1], acc[j4*4+2], acc[j4*4+3]);
    } else {
        int e = ((int)blockIdx.x - tB) * 256 + threadIdx.x;
        if (e < E) g_pos[e] = atomicAdd(&g_deg[ei[E + e]], 1);
    }
}

// ------------------------- scan (2 kernels) ---------------------------------
__global__ void k_scan1(int n) {
    __shared__ int s[SCAN_B];
    int t = threadIdx.x;
    int i = blockIdx.x * SCAN_B + t;
    int v = (i < n) ? g_deg[i] : 0;
    s[t] = v;
    __syncthreads();
#pragma unroll
    for (int d = 1; d < SCAN_B; d <<= 1) {
        int x = (t >= d) ? s[t - d] : 0;
        __syncthreads();
        s[t] += x;
        __syncthreads();
    }
    if (i < n) g_tmp[i] = s[t];                 // inclusive
    if (t == SCAN_B - 1) g_bsum[blockIdx.x] = s[t];
}

// offsets + dinv + pool zero; per-block redundant scan of <=98 block sums
__global__ void k_scan3(int n, int E, int nblk) {
    __shared__ int sb[NBLK_MAX];
    int t = threadIdx.x;
    if (t < NBLK_MAX) sb[t] = (t < nblk) ? g_bsum[t] : 0;
    __syncthreads();
#pragma unroll
    for (int d = 1; d < NBLK_MAX; d <<= 1) {
        int x = 0;
        if (t < NBLK_MAX && t >= d) x = sb[t - d];
        __syncthreads();
        if (t < NBLK_MAX) sb[t] += x;
        __syncthreads();
    }
    int i = blockIdx.x * blockDim.x + t;
    if (i < n) {
        int deg = g_deg[i];
        int blk = i / SCAN_B;
        int base = (blk == 0) ? 0 : sb[blk - 1];
        g_off[i] = g_tmp[i] - deg + base;               // exclusive
        g_dinv[i] = rsqrtf((float)(deg + 1));           // +1 self loop
    }
    if (i < G_NUM * 64) g_pool[i] = 0.f;
    if (i == 0) g_off[n] = E;
}

// place edges (atomic-free) + prescale q0 by dinv + deg re-zero for next call
__global__ void k_place(const int* __restrict__ ei, int E, int n) {
    int e = blockIdx.x * blockDim.x + threadIdx.x;
    if (e < n * 4) {                       // prescale B0 rows (N*4 float4s)
        int node = e >> 2;
        float d = g_dinv[node];
        float4* B04 = reinterpret_cast<float4*>(g_B0);
        float4 v = B04[e];
        v.x *= d; v.y *= d; v.z *= d; v.w *= d;
        B04[e] = v;
    }
    if (e < n) g_deg[e] = 0;
    if (e >= E) return;
    g_csrc[g_off[ei[E + e]] + g_pos[e]] = ei[e];
}

// ---------------------------------------------------------------------------
// Node transform (R9 shape): acc = in @ W, epilogue variants
// ---------------------------------------------------------------------------
template <int F_IN, int F_OUT, int EPI>
__global__ void k_transform(int in_sel, int out_sel,
                            const float* __restrict__ W,
                            const float* __restrict__ bout, int n)
{
    __shared__ float sW[F_IN * F_OUT];
    for (int i = threadIdx.x; i < F_IN * F_OUT; i += blockDim.x) sW[i] = W[i];
    __syncthreads();

    int node = blockIdx.x * blockDim.x + threadIdx.x;
    if (node >= n) return;

    const float4* row4 = reinterpret_cast<const float4*>(buf(in_sel)) +
                         (long long)node * (F_IN / 4);

    float acc[F_OUT];
#pragma unroll
    for (int j = 0; j < F_OUT; j++) acc[j] = 0.f;

    for (int k4 = 0; k4 < F_IN / 4; k4++) {
        float4 v4 = row4[k4];
        float vv[4] = {v4.x, v4.y, v4.z, v4.w};
#pragma unroll
        for (int u = 0; u < 4; u++) {
            int k = k4 * 4 + u;
#pragma unroll
            for (int j = 0; j < F_OUT; j++)
                acc[j] = fmaf(vv[u], sW[k * F_OUT + j], acc[j]);
        }
    }

    float di = g_dinv[node];
    float4* out4 = reinterpret_cast<float4*>(buf(out_sel)) +
                   (long long)node * (F_OUT / 4);
#pragma unroll
    for (int j4 = 0; j4 < F_OUT / 4; j4++) {
        float o[4];
#pragma unroll
        for (int u = 0; u < 4; u++) {
            float a = acc[j4 * 4 + u];
            if (EPI == 1) o[u] = fmaxf(a + bout[j4 * 4 + u], 0.f) * di;
            else          o[u] = fmaxf(a + bout[j4 * 4 + u], 0.f);
        }
        out4[j4] = make_float4(o[0], o[1], o[2], o[3]);
    }
}

// ---------------------------------------------------------------------------
// Warp-per-node gather (R13 shape, x2-unrolled edge loop)
// ---------------------------------------------------------------------------
template <int F, bool FUSED>
__global__ void k_gather(int in_sel, int out_sel,
                         const float* __restrict__ bias, int n)
{
    constexpr int L = F / 4;
    constexpr int SLOTS = 32 / L;

    int node = blockIdx.x * blockDim.y + threadIdx.y;
    if (node >= n) return;
    int lane = threadIdx.x;
    int slot = lane / L;
    int f4   = lane % L;

    const float4* In4 = reinterpret_cast<const float4*>(buf(in_sel));
    int e0 = g_off[node];
    int e1 = g_off[node + 1];

    float4 a = make_float4(0.f, 0.f, 0.f, 0.f);
    float4 b = make_float4(0.f, 0.f, 0.f, 0.f);
    if (slot == 0) a = In4[(long long)node * L + f4];   // self-loop term

    int e = e0 + slot;
    for (; e + SLOTS < e1; e += 2 * SLOTS) {
        int s0 = g_csrc[e];
        int s1 = g_csrc[e + SLOTS];
        float4 v0 = In4[(long long)s0 * L + f4];
        float4 v1 = In4[(long long)s1 * L + f4];
        a.x += v0.x; a.y += v0.y; a.z += v0.z; a.w += v0.w;
        b.x += v1.x; b.y += v1.y; b.z += v1.z; b.w += v1.w;
    }
    if (e < e1) {
        int s0 = g_csrc[e];
        float4 v0 = In4[(long long)s0 * L + f4];
        a.x += v0.x; a.y += v0.y; a.z += v0.z; a.w += v0.w;
    }
    a.x += b.x; a.y += b.y; a.z += b.z; a.w += b.w;

#pragma unroll
    for (int off = 16; off >= L; off >>= 1) {
        a.x += __shfl_xor_sync(0xffffffffu, a.x, off);
        a.y += __shfl_xor_sync(0xffffffffu, a.y, off);
        a.z += __shfl_xor_sync(0xffffffffu, a.z, off);
        a.w += __shfl_xor_sync(0xffffffffu, a.w, off);
    }

    if (slot == 0) {
        float di = g_dinv[node];
        float4 o;
        o.x = a.x * di; o.y = a.y * di; o.z = a.z * di; o.w = a.w * di;
        if (FUSED) {
            const float4 b4 = reinterpret_cast<const float4*>(bias)[f4];
            o.x = fmaxf(o.x + b4.x, 0.f) * di;
            o.y = fmaxf(o.y + b4.y, 0.f) * di;
            o.z = fmaxf(o.z + b4.z, 0.f) * di;
            o.w = fmaxf(o.w + b4.w, 0.f) * di;
        }
        reinterpret_cast<float4*>(buf(out_sel))[(long long)node * L + f4] = o;
    }
}

// ----------------- pool: segment max over sorted batch ids -----------------
__global__ void k_pool(int in_sel, const int* __restrict__ batch, int n)
{
    int f = threadIdx.x;
    int chunk = blockIdx.x * blockDim.y + threadIdx.y;
    int n0 = chunk * 16;
    if (n0 >= n) return;
    int n1 = min(n0 + 16, n);
    const float* h = buf(in_sel);

    int curg = batch[n0];
    float m = h[(long long)n0 * 64 + f];
    for (int i = n0 + 1; i < n1; i++) {
        int g = batch[i];
        float v = h[(long long)i * 64 + f];
        if (g != curg) {
            atomicMax((unsigned int*)&g_pool[curg * 64 + f], __float_as_uint(m));
            curg = g;
            m = v;
        } else {
            m = fmaxf(m, v);
        }
    }
    atomicMax((unsigned int*)&g_pool[curg * 64 + f], __float_as_uint(m));
}

// ---------------- fused MLP head (block per graph, R14-validated) -----------
__global__ void k_mlp(const float* __restrict__ W1, const float* __restrict__ b1,
                      const float* __restrict__ W2, const float* __restrict__ b2,
                      float* __restrict__ out)
{
    __shared__ float sp[64];
    __shared__ float sz[256];
    int g = blockIdx.x, j = threadIdx.x;
    if (j < 64) sp[j] = g_pool[g * 64 + j];
    __syncthreads();
    float acc = b1[j];
#pragma unroll
    for (int k = 0; k < 64; k++) acc = fmaf(sp[k], W1[k * 256 + j], acc);
    sz[j] = fmaxf(acc, 0.f);
    __syncthreads();
    float acc2 = b2[j];
#pragma unroll 8
    for (int k = 0; k < 256; k++) acc2 = fmaf(sz[k], W2[k * 256 + j], acc2);
    out[g * 256 + j] = 1.f / (1.f + expf(-acc2));
}

// ------------------------------ launch -------------------------------------
extern "C" void kernel_launch(void* const* d_in, const int* in_sizes, int n_in,
                              void* d_out, int out_size)
{
    const float* x     = (const float*)d_in[0];
    const int*   ei    = (const int*)d_in[1];    // int32 (JAX x64 disabled)
    const int*   batch = (const int*)d_in[2];
    const float* W1 = (const float*)d_in[3];
    const float* b1 = (const float*)d_in[4];
    const float* W2 = (const float*)d_in[5];
    const float* b2 = (const float*)d_in[6];
    const float* W3 = (const float*)d_in[7];
    const float* b3 = (const float*)d_in[8];
    const float* L1w = (const float*)d_in[9];
    const float* L1b = (const float*)d_in[10];
    const float* L2w = (const float*)d_in[11];
    const float* L2b = (const float*)d_in[12];
    float* out = (float*)d_out;

    int N = in_sizes[0] / 128;
    int E = in_sizes[1] / 2;
    int nblk = (N + SCAN_B - 1) / SCAN_B;
    int tB   = (N + 255) / 256;            // transform1 blocks
    int pB   = (E + 255) / 256;            // pos blocks

    // kA: transform1 (raw) overlapped with edge-rank pass
    kA      <<<tB + pB, 256>>>(x, W1, ei, N, E, tB);
    k_scan1 <<<nblk, SCAN_B>>>(N);
    k_scan3 <<<(N + 255) / 256, 256>>>(N, E, nblk);
    // place + prescale(q0 *= dinv) + deg re-zero; grid covers max(E, 4N)
    { int m = (E > 4 * N) ? E : 4 * N;
      k_place <<<(m + 255) / 256, 256>>>(ei, E, N); }

    dim3 gb(32, 8);
    int ggrid = (N + 7) / 8;

    //           q1 = relu(dinv*(q0+Σq0) + b1) * dinv       [N,16] -> buf1
    k_gather<16, true ><<<ggrid, gb>>>(0, 1, b1, N);
    // Layer 2:  m2 = dinv*(q1+Σq1)                         [N,16] -> buf0
    k_gather<16, false><<<ggrid, gb>>>(1, 0, nullptr, N);
    //           q2 = relu(m2 @ W2 + b2) * dinv             [N,32] -> buf1
    k_transform<16, 32, 1><<<(N + 127) / 128, 128>>>(0, 1, W2, b2, N);
    // Layer 3:  m3 = dinv*(q2+Σq2)                         [N,32] -> buf0
    k_gather<32, false><<<ggrid, gb>>>(1, 0, nullptr, N);
    //           h3 = relu(m3 @ W3 + b3)                    [N,64] -> buf1
    k_transform<32, 64, 2><<<(N + 127) / 128, 128>>>(0, 1, W3, b3, N);

    { dim3 pb(64, 4); int chunks = (N + 15) / 16;
      k_pool<<<(chunks + 3) / 4, pb>>>(1, batch, N); }
    k_mlp<<<G_NUM, 256>>>(L1w, L1b, L2w, L2b, out);
}